// round 4
// baseline (speedup 1.0000x reference)
#include <cuda_runtime.h>
#include <cstdint>

#define DIM      64
#define TILE_M   128
#define THREADS  128

// ---- shared memory layout (bases 1024-aligned; SW128 swizzle per tile) ----
#define SM_A_HI  0
#define SM_A_LO  (SM_A_HI + TILE_M * 128)     // 16 KB each (128 rows x 128 B)
#define SM_B_HI  (SM_A_LO + TILE_M * 128)
#define SM_B_LO  (SM_B_HI + DIM * 128)        // 8 KB each (64 rows x 128 B)
#define SM_N2    (SM_B_LO + DIM * 128)        // 128 floats
#define SM_TOTAL (SM_N2 + TILE_M * 4)         // 49664 B

static __device__ __forceinline__ uint32_t smem_u32(const void* p) {
    uint32_t a;
    asm("{ .reg .u64 t; cvta.to.shared.u64 t, %1; cvt.u32.u64 %0, t; }"
        : "=r"(a) : "l"(p));
    return a;
}

static __device__ __forceinline__ uint32_t sw128(uint32_t off) {
    return off ^ ((off >> 3) & 0x70u);
}

// pack two fp32 -> bf16x2 (a low half, b high half) + residual pair
static __device__ __forceinline__ void split_pair(float a, float b,
                                                  uint32_t& hi, uint32_t& lo) {
    uint32_t h;
    asm("cvt.rn.bf16x2.f32 %0, %1, %2;" : "=r"(h) : "f"(b), "f"(a));
    float ha = __uint_as_float(h << 16);
    float hb = __uint_as_float(h & 0xFFFF0000u);
    uint32_t l;
    float la = a - ha, lb = b - hb;
    asm("cvt.rn.bf16x2.f32 %0, %1, %2;" : "=r"(l) : "f"(lb), "f"(la));
    hi = h; lo = l;
}

static __device__ __forceinline__ void ldsm4(uint32_t* r, uint32_t addr) {
    asm volatile("ldmatrix.sync.aligned.m8n8.x4.shared.b16 {%0,%1,%2,%3}, [%4];"
                 : "=r"(r[0]), "=r"(r[1]), "=r"(r[2]), "=r"(r[3]) : "r"(addr));
}

static __device__ __forceinline__ void mma_bf16(float* d, const uint32_t* a,
                                                uint32_t b0, uint32_t b1) {
    asm volatile(
        "mma.sync.aligned.m16n8k16.row.col.f32.bf16.bf16.f32 "
        "{%0,%1,%2,%3}, {%4,%5,%6,%7}, {%8,%9}, {%0,%1,%2,%3};"
        : "+f"(d[0]), "+f"(d[1]), "+f"(d[2]), "+f"(d[3])
        : "r"(a[0]), "r"(a[1]), "r"(a[2]), "r"(a[3]), "r"(b0), "r"(b1));
}

static __device__ __forceinline__ float bf16lo(uint32_t v) {
    return __uint_as_float(v << 16);
}
static __device__ __forceinline__ float bf16hi(uint32_t v) {
    return __uint_as_float(v & 0xFFFF0000u);
}

__global__ void __launch_bounds__(THREADS, 4)
qmeas_kernel(const float* __restrict__ x, const float* __restrict__ rho,
             float* __restrict__ out, int nrows) {
    extern __shared__ char smem[];
    const uint32_t sb = smem_u32(smem);
    float* n2s = (float*)(smem + SM_N2);

    const int tid  = threadIdx.x;
    const int lane = tid & 31;
    const int wid  = tid >> 5;

    const long row = (long)blockIdx.x * TILE_M + tid;
    const bool valid = (row < (long)nrows);

    // ---- load my x row (fp32), accumulate norm^2 ----
    float xv[DIM];
    float norm2 = 0.f;
    if (valid) {
        const float4* xp = (const float4*)(x + (size_t)row * DIM);
        #pragma unroll
        for (int i = 0; i < DIM / 4; i++) {
            float4 v = xp[i];
            xv[4*i+0] = v.x; xv[4*i+1] = v.y; xv[4*i+2] = v.z; xv[4*i+3] = v.w;
            norm2 += v.x*v.x + v.y*v.y + v.z*v.z + v.w*v.w;
        }
    } else {
        #pragma unroll
        for (int i = 0; i < DIM; i++) xv[i] = 0.f;
    }
    n2s[tid] = norm2;

    // ---- split x row -> bf16 hi/lo SW128 tiles (8 STS.128 per tile) ----
    #pragma unroll
    for (int c = 0; c < 8; c++) {
        uint32_t hi[4], lo[4];
        #pragma unroll
        for (int p = 0; p < 4; p++)
            split_pair(xv[c*8 + 2*p], xv[c*8 + 2*p + 1], hi[p], lo[p]);
        uint32_t off = sw128((uint32_t)tid * 128u + (uint32_t)c * 16u);
        asm volatile("st.shared.v4.b32 [%0], {%1,%2,%3,%4};"
                     :: "r"(sb + SM_A_HI + off), "r"(hi[0]), "r"(hi[1]), "r"(hi[2]), "r"(hi[3])
                     : "memory");
        asm volatile("st.shared.v4.b32 [%0], {%1,%2,%3,%4};"
                     :: "r"(sb + SM_A_LO + off), "r"(lo[0]), "r"(lo[1]), "r"(lo[2]), "r"(lo[3])
                     : "memory");
    }

    // ---- load + split rho (64x64): thread t -> row t/2, cols (t&1)*32.. ----
    {
        const int mrow = tid >> 1;
        const int cb = (tid & 1) * 32;
        const float4* mp = (const float4*)(rho + mrow * DIM + cb);
        #pragma unroll
        for (int c = 0; c < 4; c++) {
            float4 v0 = mp[2*c + 0];
            float4 v1 = mp[2*c + 1];
            float e[8] = {v0.x, v0.y, v0.z, v0.w, v1.x, v1.y, v1.z, v1.w};
            uint32_t hi[4], lo[4];
            #pragma unroll
            for (int p = 0; p < 4; p++)
                split_pair(e[2*p], e[2*p + 1], hi[p], lo[p]);
            uint32_t off = sw128((uint32_t)mrow * 128u + (uint32_t)(cb + c*8) * 2u);
            asm volatile("st.shared.v4.b32 [%0], {%1,%2,%3,%4};"
                         :: "r"(sb + SM_B_HI + off), "r"(hi[0]), "r"(hi[1]), "r"(hi[2]), "r"(hi[3])
                         : "memory");
            asm volatile("st.shared.v4.b32 [%0], {%1,%2,%3,%4};"
                         :: "r"(sb + SM_B_LO + off), "r"(lo[0]), "r"(lo[1]), "r"(lo[2]), "r"(lo[3])
                         : "memory");
        }
    }
    __syncthreads();

    // ---- GEMM: Y[128,64] = X * rho^T via mma.sync m16n8k16 bf16 (3-term split)
    // warp w owns rows [w*32, w*32+32) = m-tiles {2w, 2w+1}
    const int mbase = wid * 32;
    const int lane7 = lane & 7;
    const int agrp  = lane >> 3;

    float acc[2][8][4];
    #pragma unroll
    for (int t = 0; t < 2; t++)
        #pragma unroll
        for (int n = 0; n < 8; n++)
            #pragma unroll
            for (int q = 0; q < 4; q++) acc[t][n][q] = 0.f;

    // ldmatrix.x4 lane->address mapping:
    // A: grp0 rows m0-7/k0-7, grp1 m8-15/k0-7, grp2 m0-7/k8-15, grp3 m8-15/k8-15
    // B: grp0 n0-7/k0-7,  grp1 n0-7/k8-15,  grp2 n8-15/k0-7,  grp3 n8-15/k8-15
    const uint32_t kA = (uint32_t)((agrp >> 1) * 16);
    const uint32_t kB = (uint32_t)((agrp & 1) * 16);
    uint32_t arow[2], brow[4];
    #pragma unroll
    for (int t = 0; t < 2; t++)
        arow[t] = (uint32_t)(mbase + t*16 + (agrp & 1)*8 + lane7) * 128u;
    #pragma unroll
    for (int p = 0; p < 4; p++)
        brow[p] = (uint32_t)(p*16 + (agrp >> 1)*8 + lane7) * 128u;

    #pragma unroll
    for (int kk = 0; kk < 4; kk++) {
        const uint32_t kb = (uint32_t)(kk * 32);
        uint32_t ah[2][4], al[2][4];
        #pragma unroll
        for (int t = 0; t < 2; t++) {
            uint32_t off = sw128(arow[t] + kb + kA);
            ldsm4(ah[t], sb + SM_A_HI + off);
            ldsm4(al[t], sb + SM_A_LO + off);
        }
        uint32_t bf[4][4];
        #pragma unroll
        for (int p = 0; p < 4; p++) {
            uint32_t off = sw128(brow[p] + kb + kB);
            ldsm4(bf[p], sb + SM_B_HI + off);
        }
        #pragma unroll
        for (int t = 0; t < 2; t++)
            #pragma unroll
            for (int p = 0; p < 4; p++) {
                mma_bf16(acc[t][2*p],     ah[t], bf[p][0], bf[p][1]);
                mma_bf16(acc[t][2*p + 1], ah[t], bf[p][2], bf[p][3]);
                mma_bf16(acc[t][2*p],     al[t], bf[p][0], bf[p][1]);
                mma_bf16(acc[t][2*p + 1], al[t], bf[p][2], bf[p][3]);
            }
        #pragma unroll
        for (int p = 0; p < 4; p++) {
            uint32_t off = sw128(brow[p] + kb + kB);
            ldsm4(bf[p], sb + SM_B_LO + off);
        }
        #pragma unroll
        for (int t = 0; t < 2; t++)
            #pragma unroll
            for (int p = 0; p < 4; p++) {
                mma_bf16(acc[t][2*p],     ah[t], bf[p][0], bf[p][1]);
                mma_bf16(acc[t][2*p + 1], ah[t], bf[p][2], bf[p][3]);
            }
    }

    // ---- epilogue: dot(x, y) per row; x reconstructed from hi+lo smem tiles
    // c-frag: {c0,c1} -> (r0, cols cq, cq+1), {c2,c3} -> (r0+8, cols cq, cq+1)
    const int r0 = lane >> 2;
    const int cq = (lane & 3) * 2;
    float dred[2][2];
    #pragma unroll
    for (int t = 0; t < 2; t++) {
        float d0 = 0.f, d1 = 0.f;
        const int rA = mbase + t*16 + r0;
        const int rB = rA + 8;
        #pragma unroll
        for (int n = 0; n < 8; n++) {
            const uint32_t cbyte = (uint32_t)(n*8 + cq) * 2u;
            uint32_t offA = sw128((uint32_t)rA * 128u + cbyte);
            uint32_t offB = sw128((uint32_t)rB * 128u + cbyte);
            uint32_t hA, lA, hB, lB;
            asm volatile("ld.shared.b32 %0, [%1];" : "=r"(hA) : "r"(sb + SM_A_HI + offA));
            asm volatile("ld.shared.b32 %0, [%1];" : "=r"(lA) : "r"(sb + SM_A_LO + offA));
            asm volatile("ld.shared.b32 %0, [%1];" : "=r"(hB) : "r"(sb + SM_A_HI + offB));
            asm volatile("ld.shared.b32 %0, [%1];" : "=r"(lB) : "r"(sb + SM_A_LO + offB));
            float xa0 = bf16lo(hA) + bf16lo(lA);
            float xa1 = bf16hi(hA) + bf16hi(lA);
            float xb0 = bf16lo(hB) + bf16lo(lB);
            float xb1 = bf16hi(hB) + bf16hi(lB);
            d0 += xa0 * acc[t][n][0] + xa1 * acc[t][n][1];
            d1 += xb0 * acc[t][n][2] + xb1 * acc[t][n][3];
        }
        // reduce across the 4 lanes of the quad (they cover all 64 cols)
        d0 += __shfl_xor_sync(0xFFFFFFFFu, d0, 1);
        d0 += __shfl_xor_sync(0xFFFFFFFFu, d0, 2);
        d1 += __shfl_xor_sync(0xFFFFFFFFu, d1, 1);
        d1 += __shfl_xor_sync(0xFFFFFFFFu, d1, 2);
        dred[t][0] = d0;
        dred[t][1] = d1;
    }

    if ((lane & 3) == 0) {
        #pragma unroll
        for (int t = 0; t < 2; t++) {
            #pragma unroll
            for (int h = 0; h < 2; h++) {
                const int lrow = mbase + t*16 + r0 + h*8;
                const long grow = (long)blockIdx.x * TILE_M + lrow;
                if (grow < (long)nrows)
                    out[grow] = n2s[lrow] * dred[t][h];
            }
        }
    }
}

extern "C" void kernel_launch(void* const* d_in, const int* in_sizes, int n_in,
                              void* d_out, int out_size) {
    const float* x   = (const float*)d_in[0];
    const float* rho = (const float*)d_in[1];
    float* out = (float*)d_out;
    const int nrows = out_size;

    cudaFuncSetAttribute(qmeas_kernel,
                         cudaFuncAttributeMaxDynamicSharedMemorySize, SM_TOTAL);

    const int grid = (nrows + TILE_M - 1) / TILE_M;
    qmeas_kernel<<<grid, THREADS, SM_TOTAL>>>(x, rho, out, nrows);
}